// round 14
// baseline (speedup 1.0000x reference)
#include <cuda_runtime.h>
#include <math.h>
#include <stdint.h>

#define B_ 2
#define T_ 2048
#define C_ 2048
#define H_ 16
#define D_ 128
#define M_ (B_*T_)   // 4096

// ---------------- scratch (device globals; no allocation allowed) ----------------
__device__ float g_qkv[M_ * 3 * C_];           // [4096, 6144] natural
__device__ float g_q[B_ * H_ * T_ * D_];       // [B,H,T,D] (tf32-rounded)
__device__ float g_k[B_ * H_ * T_ * D_];
__device__ float g_v[B_ * H_ * T_ * D_];
__device__ float g_y[M_ * C_];                 // attention out, k-permuted tf32
__device__ float g_xt[M_ * C_];                // x, k-permuted tf32
__device__ float g_wq[3 * C_ * C_];            // w_qkv^T [6144][2048], k-permuted tf32
__device__ float g_wo[C_ * C_];                // w_out^T [2048][2048], k-permuted tf32

// ============================ PTX helpers ========================================
__device__ __forceinline__ uint32_t smem_u32(const void* p) {
    return (uint32_t)__cvta_generic_to_shared(p);
}
__device__ __forceinline__ uint32_t tf32b(float x) {   // fp32 -> tf32 bits, rna
    uint32_t u;
    asm("cvt.rna.tf32.f32 %0, %1;" : "=r"(u) : "f"(x));
    return u;
}
__device__ __forceinline__ float tf32f(float x) { return __uint_as_float(tf32b(x)); }

__device__ __forceinline__ void cp_async16(uint32_t s, const void* g) {
    asm volatile("cp.async.cg.shared.global [%0], [%1], 16;" :: "r"(s), "l"(g));
}
#define CP_ASYNC_COMMIT() asm volatile("cp.async.commit_group;" ::: "memory")
#define CP_ASYNC_WAIT(n)  asm volatile("cp.async.wait_group %0;" :: "n"(n) : "memory")

__device__ __forceinline__ void mma_tf32(float* d, const uint32_t* a, const uint32_t* b) {
    asm volatile(
        "mma.sync.aligned.m16n8k8.row.col.f32.tf32.tf32.f32 "
        "{%0,%1,%2,%3}, {%4,%5,%6,%7}, {%8,%9}, {%0,%1,%2,%3};"
        : "+f"(d[0]), "+f"(d[1]), "+f"(d[2]), "+f"(d[3])
        : "r"(a[0]), "r"(a[1]), "r"(a[2]), "r"(a[3]), "r"(b[0]), "r"(b[1]));
}

// ===== tensor-core tf32 GEMM v3: 4-stage BK=16 pipeline, k-permuted inputs =======
// C[M,N] = A[M,K] @ Bt[N,K]^T.  Block 128x128, 8 warps (4x2), warp tile 32x64.
#define GSTR 24                                // floats per row (16 data + 8 pad)
#define GBUF (128*GSTR)                        // 3072 floats per operand stage
#define NSTAGE 4
#define G_SMEM_BYTES (NSTAGE * 2 * GBUF * 4)   // 98304 B

__global__ __launch_bounds__(256, 2)
void gemm_mma_tf32(const float* __restrict__ A, const float* __restrict__ Bt,
                   float* __restrict__ Cm, int M, int N, int K) {
    extern __shared__ __align__(16) float sm[];
    float* Asm = sm;                     // [NSTAGE][GBUF]
    float* Bsm = sm + NSTAGE * GBUF;     // [NSTAGE][GBUF]

    const int tid = threadIdx.x;
    const int wid = tid >> 5, lane = tid & 31;
    const int g = lane >> 2, tg = lane & 3;
    const int warp_m = (wid >> 1) * 32;
    const int warp_n = (wid & 1) * 64;
    const int m0 = blockIdx.y * 128;
    const int n0 = blockIdx.x * 128;

    const uint32_t aS = smem_u32(Asm);
    const uint32_t bS = smem_u32(Bsm);

    float acc[2][8][4];
    #pragma unroll
    for (int i = 0; i < 2; i++)
        #pragma unroll
        for (int j = 0; j < 8; j++)
            #pragma unroll
            for (int q = 0; q < 4; q++) acc[i][j][q] = 0.f;

    const int ntiles = K >> 4;

    // stage loader: A,B each 128 rows x 16 floats (512 x 16B chunks apiece)
    auto load_tile = [&](int kt, int s) {
        const int kbase = kt << 4;
        const uint32_t aDst = aS + s * GBUF * 4;
        const uint32_t bDst = bS + s * GBUF * 4;
        #pragma unroll
        for (int u = 0; u < 2; u++) {
            const int e = u * 256 + tid;
            const int row = e >> 2, c4 = e & 3;
            cp_async16(aDst + (row * GSTR + c4 * 4) * 4,
                       A + (size_t)(m0 + row) * K + kbase + c4 * 4);
        }
        #pragma unroll
        for (int u = 0; u < 2; u++) {
            const int e = u * 256 + tid;
            const int row = e >> 2, c4 = e & 3;
            cp_async16(bDst + (row * GSTR + c4 * 4) * 4,
                       Bt + (size_t)(n0 + row) * K + kbase + c4 * 4);
        }
        CP_ASYNC_COMMIT();
    };

    // prologue: fill 3 stages
    load_tile(0, 0);
    load_tile(1, 1);
    load_tile(2, 2);

    for (int kt = 0; kt < ntiles; kt++) {
        CP_ASYNC_WAIT(2);
        __syncthreads();

        if (kt + 3 < ntiles) load_tile(kt + 3, (kt + 3) & (NSTAGE - 1));

        const float* As = Asm + (kt & (NSTAGE - 1)) * GBUF;
        const float* Bs = Bsm + (kt & (NSTAGE - 1)) * GBUF;

        #pragma unroll
        for (int kk8 = 0; kk8 < 2; kk8++) {
            const int kb = kk8 * 8 + tg * 2;
            uint32_t afr[2][4], bfr[8][2];
            #pragma unroll
            for (int mt = 0; mt < 2; mt++) {
                const int r = warp_m + mt * 16 + g;
                float2 lo = *(const float2*)&As[r * GSTR + kb];
                float2 hi = *(const float2*)&As[(r + 8) * GSTR + kb];
                afr[mt][0] = __float_as_uint(lo.x);
                afr[mt][1] = __float_as_uint(hi.x);
                afr[mt][2] = __float_as_uint(lo.y);
                afr[mt][3] = __float_as_uint(hi.y);
            }
            #pragma unroll
            for (int nt = 0; nt < 8; nt++) {
                const int c = warp_n + nt * 8 + g;
                float2 bb = *(const float2*)&Bs[c * GSTR + kb];
                bfr[nt][0] = __float_as_uint(bb.x);
                bfr[nt][1] = __float_as_uint(bb.y);
            }
            #pragma unroll
            for (int mt = 0; mt < 2; mt++)
                #pragma unroll
                for (int nt = 0; nt < 8; nt++)
                    mma_tf32(acc[mt][nt], afr[mt], bfr[nt]);
        }
        // no trailing sync: slot reuse is guarded by the top-of-loop barrier
    }

    #pragma unroll
    for (int mt = 0; mt < 2; mt++) {
        const int r = m0 + warp_m + mt * 16 + g;
        #pragma unroll
        for (int nt = 0; nt < 8; nt++) {
            const int c = n0 + warp_n + nt * 8 + tg * 2;
            *(float2*)(Cm + (size_t)r * N + c)       = make_float2(acc[mt][nt][0], acc[mt][nt][1]);
            *(float2*)(Cm + (size_t)(r + 8) * N + c) = make_float2(acc[mt][nt][2], acc[mt][nt][3]);
        }
    }
}

// --------- staging: tf32 round + k-group permutation [0,4,1,5,2,6,3,7] ----------
__global__ void round_perm_copy(const float* __restrict__ in, float* __restrict__ out) {
    const int i = (blockIdx.x * blockDim.x + threadIdx.x) * 8;
    float4 v0 = *(const float4*)(in + i);
    float4 v1 = *(const float4*)(in + i + 4);
    *(float4*)(out + i)     = make_float4(tf32f(v0.x), tf32f(v1.x), tf32f(v0.y), tf32f(v1.y));
    *(float4*)(out + i + 4) = make_float4(tf32f(v0.z), tf32f(v1.z), tf32f(v0.w), tf32f(v1.w));
}

// W[K,N] -> WT[N,K] transposed + tf32-rounded + k-permuted
__global__ void transpose_perm_tf32(const float* __restrict__ W, float* __restrict__ WT,
                                    int K, int N) {
    __shared__ float tile[32][33];
    const int kb = blockIdx.y * 32, nb = blockIdx.x * 32;
    const int tx = threadIdx.x & 31, ty = threadIdx.x >> 5;
    #pragma unroll
    for (int r = ty; r < 32; r += 8)
        tile[r][tx] = W[(size_t)(kb + r) * N + nb + tx];
    __syncthreads();
    const int kperm = (tx & ~7) + ((tx & 3) << 1) + ((tx >> 2) & 1);
    #pragma unroll
    for (int r = ty; r < 32; r += 8)
        WT[(size_t)(nb + r) * K + kb + kperm] = tf32f(tile[tx][r]);
}

// ---------------- RoPE + split + fold 1/sqrt(D) into Q, tf32-round outputs ------
__global__ void rope_split_kernel(const float* __restrict__ qkv,
                                  float* __restrict__ Qo, float* __restrict__ Ko,
                                  float* __restrict__ Vo) {
    int idx = blockIdx.x * blockDim.x + threadIdx.x;
    if (idx >= B_ * T_ * H_ * 64) return;
    const int i = idx & 63;
    const int h = (idx >> 6) & 15;
    const int t = (idx >> 10) & (T_ - 1);
    const int b = idx >> 21;

    const float* row = qkv + (size_t)(b * T_ + t) * (3 * C_);
    const float inv = powf(10000.f, -(float)i / 64.f);
    const float f = (float)t * inv;
    float s, c;
    sincosf(f, &s, &c);

    const float q0 = row[h * D_ + i],            q1 = row[h * D_ + i + 64];
    const float k0 = row[C_ + h * D_ + i],       k1 = row[C_ + h * D_ + i + 64];
    const float v0 = row[2 * C_ + h * D_ + i],   v1 = row[2 * C_ + h * D_ + i + 64];

    const size_t o = ((size_t)(b * H_ + h) * T_ + t) * D_ + i;
    const float sc = 0.08838834764831845f;   // 1/sqrt(128)
    Qo[o]      = tf32f((q0 * c - q1 * s) * sc);
    Qo[o + 64] = tf32f((q1 * c + q0 * s) * sc);
    Ko[o]      = tf32f(k0 * c - k1 * s);
    Ko[o + 64] = tf32f(k1 * c + k0 * s);
    Vo[o]      = tf32f(v0);
    Vo[o + 64] = tf32f(v1);
}

// ============ tensor-core flash attention v3: split K/V waits ====================
#define QSTR 132
#define KSTR 132
#define PSTR 66
#define VSTR 136
#define FA_QOFF 0
#define FA_K0 (128*QSTR)
#define FA_K1 (FA_K0 + 64*KSTR)
#define FA_V0 (FA_K1 + 64*KSTR)
#define FA_V1 (FA_V0 + 64*VSTR)
#define FA_SMEM_FLOATS (FA_V1 + 64*VSTR)
#define FA_SMEM_BYTES (FA_SMEM_FLOATS * 4)   // 204800

__global__ __launch_bounds__(256, 1)
void flash_attn_tc(const float* __restrict__ Qg, const float* __restrict__ Kg,
                   const float* __restrict__ Vg, float* __restrict__ Yg) {
    extern __shared__ __align__(16) float sm[];
    float* Qs = sm + FA_QOFF;

    const int tid = threadIdx.x;
    const int w = tid >> 5, lane = tid & 31;
    const int g = lane >> 2, tg = lane & 3;

    const int qi = gridDim.x - 1 - blockIdx.x;   // heavy blocks first
    const int h = blockIdx.y;
    const int b = blockIdx.z;
    const size_t bh = (size_t)(b * H_ + h);
    const float* Qp = Qg + bh * T_ * D_ + (size_t)qi * 128 * D_;
    const float* Kb = Kg + bh * T_ * D_;
    const float* Vb = Vg + bh * T_ * D_;

    const uint32_t smB = smem_u32(sm);
    const uint32_t kOff[2] = {smB + FA_K0 * 4, smB + FA_K1 * 4};
    const uint32_t vOff[2] = {smB + FA_V0 * 4, smB + FA_V1 * 4};

    auto load_k = [&](int chunk, int buf) {
        const float* Kc = Kb + (size_t)chunk * 64 * D_;
        #pragma unroll
        for (int u = 0; u < 8; u++) {
            const int e = u * 256 + tid;
            const int r = e >> 5, c4 = e & 31;
            cp_async16(kOff[buf] + (r * KSTR + c4 * 4) * 4, Kc + r * D_ + c4 * 4);
        }
    };
    auto load_v = [&](int chunk, int buf) {
        const float* Vc = Vb + (size_t)chunk * 64 * D_;
        #pragma unroll
        for (int u = 0; u < 8; u++) {
            const int e = u * 256 + tid;
            const int r = e >> 5, c4 = e & 31;
            cp_async16(vOff[buf] + (r * VSTR + c4 * 4) * 4, Vc + r * D_ + c4 * 4);
        }
    };

    // prologue: group1 = Q + K0, group2 = V0
    #pragma unroll
    for (int u = 0; u < 16; u++) {
        const int e = u * 256 + tid;
        const int r = e >> 5, c4 = e & 31;
        cp_async16(smB + (FA_QOFF + r * QSTR + c4 * 4) * 4, Qp + r * D_ + c4 * 4);
    }
    load_k(0, 0);
    CP_ASYNC_COMMIT();
    load_v(0, 0);
    CP_ASYNC_COMMIT();

    const int row0 = w * 16 + g;
    const int nk = 2 * (qi + 1);

    float o[16][4];
    float m0 = -INFINITY, m1 = -INFINITY, l0 = 0.f, l1 = 0.f;
    #pragma unroll
    for (int nt = 0; nt < 16; nt++)
        #pragma unroll
        for (int q = 0; q < 4; q++) o[nt][q] = 0.f;

    for (int i = 0; i < nk; i++) {
        const int kb = i & 1;
        float* Ks = sm + (kb ? FA_K1 : FA_K0);
        float* Ps = Ks;
        float* Vs = sm + (kb ? FA_V1 : FA_V0);

        CP_ASYNC_WAIT(1);        // K_i (and Q) ready; V_i may still stream
        __syncthreads();

        float s[8][4];
        #pragma unroll
        for (int nt = 0; nt < 8; nt++)
            #pragma unroll
            for (int q = 0; q < 4; q++) s[nt][q] = 0.f;

        #pragma unroll
        for (int kk = 0; kk < 16; kk++) {
            const int d0 = kk * 8;
            uint32_t a[4];
            a[0] = __float_as_uint(Qs[row0 * QSTR + d0 + tg]);
            a[1] = __float_as_uint(Qs[(row0 + 8) * QSTR + d0 + tg]);
            a[2] = __float_as_uint(Qs[row0 * QSTR + d0 + tg + 4]);
            a[3] = __float_as_uint(Qs[(row0 + 8) * QSTR + d0 + tg + 4]);
            #pragma unroll
            for (int nt = 0; nt < 8; nt++) {
                const int c = nt * 8 + g;
                uint32_t bf[2];
                bf[0] = __float_as_uint(Ks[c * KSTR + d0 + tg]);
                bf[1] = __float_as_uint(Ks[c * KSTR + d0 + tg + 4]);
                mma_tf32(s[nt], a, bf);
            }
        }

        // all warps done READING K before any warp overwrites it with P
        __syncthreads();

        if (i >= 2 * qi) {
            const int rg0 = qi * 128 + row0;
            const int cb = i * 64;
            #pragma unroll
            for (int nt = 0; nt < 8; nt++) {
                const int c0 = cb + nt * 8 + 2 * tg;
                if (c0 > rg0)         s[nt][0] = -INFINITY;
                if (c0 + 1 > rg0)     s[nt][1] = -INFINITY;
                if (c0 > rg0 + 8)     s[nt][2] = -INFINITY;
                if (c0 + 1 > rg0 + 8) s[nt][3] = -INFINITY;
            }
        }

        float ml0 = -INFINITY, ml1 = -INFINITY;
        #pragma unroll
        for (int nt = 0; nt < 8; nt++) {
            ml0 = fmaxf(ml0, fmaxf(s[nt][0], s[nt][1]));
            ml1 = fmaxf(ml1, fmaxf(s[nt][2], s[nt][3]));
        }
        #pragma unroll
        for (int off = 1; off <= 2; off <<= 1) {
            ml0 = fmaxf(ml0, __shfl_xor_sync(0xffffffffu, ml0, off));
            ml1 = fmaxf(ml1, __shfl_xor_sync(0xffffffffu, ml1, off));
        }
        const float mn0 = fmaxf(m0, ml0), mn1 = fmaxf(m1, ml1);
        const float al0 = __expf(m0 - mn0), al1 = __expf(m1 - mn1);
        m0 = mn0; m1 = mn1;

        float sl0 = 0.f, sl1 = 0.f;
        #pragma unroll
        for (int nt = 0; nt < 8; nt++) {
            const int c0 = nt * 8 + 2 * tg;
            float e0 = __expf(s[nt][0] - m0);
            float e1 = __expf(s[nt][1] - m0);
            float e2 = __expf(s[nt][2] - m1);
            float e3 = __expf(s[nt][3] - m1);
            sl0 += e0 + e1;
            sl1 += e2 + e3;
            *(float2*)&Ps[row0 * PSTR + c0] = make_float2(tf32f(e0), tf32f(e1));
            *(float2*)&Ps[(row0 + 8) * PSTR + c0] = make_float2(tf32f(e2), tf32f(e3));
        }
        #pragma unroll
        for (int off = 1; off <= 2; off <<= 1) {
            sl0 += __shfl_xor_sync(0xffffffffu, sl0, off);
            sl1 += __shfl_xor_sync(0xffffffffu, sl1, off);
        }
        l0 = l0 * al0 + sl0;
        l1 = l1 * al1 + sl1;

        CP_ASYNC_WAIT(0);        // V_i ready
        __syncthreads();

        if (i + 1 < nk) {
            load_k(i + 1, kb ^ 1);
            CP_ASYNC_COMMIT();
            load_v(i + 1, kb ^ 1);
            CP_ASYNC_COMMIT();
        }

        #pragma unroll
        for (int nt = 0; nt < 16; nt++) {
            o[nt][0] *= al0; o[nt][1] *= al0;
            o[nt][2] *= al1; o[nt][3] *= al1;
        }

        #pragma unroll
        for (int kk = 0; kk < 8; kk++) {
            const int k0 = kk * 8;
            uint32_t a[4];
            a[0] = __float_as_uint(Ps[row0 * PSTR + k0 + tg]);
            a[1] = __float_as_uint(Ps[(row0 + 8) * PSTR + k0 + tg]);
            a[2] = __float_as_uint(Ps[row0 * PSTR + k0 + tg + 4]);
            a[3] = __float_as_uint(Ps[(row0 + 8) * PSTR + k0 + tg + 4]);
            #pragma unroll
            for (int nt = 0; nt < 16; nt++) {
                const int c = nt * 8 + g;
                uint32_t bf[2];
                bf[0] = __float_as_uint(Vs[(k0 + tg) * VSTR + c]);
                bf[1] = __float_as_uint(Vs[(k0 + tg + 4) * VSTR + c]);
                mma_tf32(o[nt], a, bf);
            }
        }
    }

    // ---- epilogue: normalize, tf32-round, write y k-PERMUTED for proj GEMM ----
    const float inv0 = 1.0f / l0, inv1 = 1.0f / l1;
    const int gr0 = qi * 128 + row0;
    const int p0 = ((2 * tg) & 3) * 2 + (tg >> 1);
    #pragma unroll
    for (int nt = 0; nt < 16; nt++) {
        const int gb = h * D_ + nt * 8;
        float* y0 = Yg + ((size_t)b * T_ + gr0) * C_ + gb;
        float* y1 = Yg + ((size_t)b * T_ + gr0 + 8) * C_ + gb;
        y0[p0]     = tf32f(o[nt][0] * inv0);
        y0[p0 + 2] = tf32f(o[nt][1] * inv0);
        y1[p0]     = tf32f(o[nt][2] * inv1);
        y1[p0 + 2] = tf32f(o[nt][3] * inv1);
    }
}

// ------------------------------------ launch -------------------------------------
extern "C" void kernel_launch(void* const* d_in, const int* in_sizes, int n_in,
                              void* d_out, int out_size) {
    const float* x     = (const float*)d_in[0];
    const float* w_qkv = (const float*)d_in[1];
    const float* w_out = (const float*)d_in[2];
    float* out = (float*)d_out;

    float *qkv, *q, *k, *v, *y, *xt, *wq, *wo;
    cudaGetSymbolAddress((void**)&qkv, g_qkv);
    cudaGetSymbolAddress((void**)&q, g_q);
    cudaGetSymbolAddress((void**)&k, g_k);
    cudaGetSymbolAddress((void**)&v, g_v);
    cudaGetSymbolAddress((void**)&y, g_y);
    cudaGetSymbolAddress((void**)&xt, g_xt);
    cudaGetSymbolAddress((void**)&wq, g_wq);
    cudaGetSymbolAddress((void**)&wo, g_wo);

    cudaFuncSetAttribute(gemm_mma_tf32, cudaFuncAttributeMaxDynamicSharedMemorySize,
                         G_SMEM_BYTES);
    cudaFuncSetAttribute(flash_attn_tc, cudaFuncAttributeMaxDynamicSharedMemorySize,
                         FA_SMEM_BYTES);

    // staging: tf32 round + k-permute (x) / transpose + permute (weights)
    round_perm_copy<<<(M_ * C_) / 2048, 256>>>(x, xt);
    transpose_perm_tf32<<<dim3(3 * C_ / 32, C_ / 32), 256>>>(w_qkv, wq, C_, 3 * C_);
    transpose_perm_tf32<<<dim3(C_ / 32, C_ / 32), 256>>>(w_out, wo, C_, C_);

    // 1) qkv = x @ w_qkv
    dim3 g1(3 * C_ / 128, M_ / 128);
    gemm_mma_tf32<<<g1, 256, G_SMEM_BYTES>>>(xt, wq, qkv, M_, 3 * C_, C_);

    // 2) rope + split into Q,K,V [B,H,T,D] (tf32-rounded)
    const int nrope = B_ * T_ * H_ * 64;
    rope_split_kernel<<<nrope / 256, 256>>>(qkv, q, k, v);

    // 3) pipelined tensor-core causal flash attention -> y (k-permuted)
    dim3 g2(T_ / 128, H_, B_);
    flash_attn_tc<<<g2, 256, FA_SMEM_BYTES>>>(q, k, v, y);

    // 4) out = y @ w_out
    dim3 g3(C_ / 128, M_ / 128);
    gemm_mma_tf32<<<g3, 256, G_SMEM_BYTES>>>(y, wo, out, M_, C_, C_);
}